// round 17
// baseline (speedup 1.0000x reference)
#include <cuda_runtime.h>

// SocialCircleLayer: B=8192 rows, N=128 neighbors, T=8, P=8.
// R17: R16 warp-per-row design with the count bug fixed. R16 ran cnt through
// the width-4 shuffle tree, but every lane already held the FULL partition
// count (m is warp-wide) -> 4x overcount -> rel_err 0.74999 (== 1 - 1/4).
// cnt is now excluded from the tree. Design unchanged: one warp owns one
// row (4 groups x 32 neighbors), register-only bucketed reduction, no smem,
// no barriers, no scratch, no second kernel.

#define NNEI   128
#define PARTS  8
#define MU_F     1e-4f
#define CEPS_F   1e-4f
#define TWO_PI_F 6.283185307179586f
#define PI_F     3.14159265358979f
#define PIO2_F   1.5707963267949f
#define PIO4_F   0.78539816339745f
#define TAN_PIO8 0.41421356237f

__device__ __forceinline__ float approx_len(float x2) {
    float r;
    asm("rsqrt.approx.f32 %0, %1;" : "=f"(r) : "f"(x2));
    float len = x2 * r;
    return (x2 > 0.0f) ? len : 0.0f;
}

// atan2 in [0, 2*pi): |err| < ~3e-7 rad (validated: rel_err 6.6e-8).
__device__ __forceinline__ float atan2_2pi(float y, float x) {
    const float ax = fabsf(x);
    const float ay = fabsf(y);
    const float mx = fmaxf(ax, ay);
    const float mn = fminf(ax, ay);
    float t = (mx == 0.0f) ? 0.0f : __fdividef(mn, mx);

    const bool red = (t > TAN_PIO8);
    const float u  = red ? __fdividef(t - 1.0f, t + 1.0f) : t;

    const float z = u * u;
    float q;
    q = -1.0f / 15.0f;
    q = fmaf(q, z,  1.0f / 13.0f);
    q = fmaf(q, z, -1.0f / 11.0f);
    q = fmaf(q, z,  1.0f /  9.0f);
    q = fmaf(q, z, -1.0f /  7.0f);
    q = fmaf(q, z,  1.0f /  5.0f);
    q = fmaf(q, z, -1.0f /  3.0f);
    float a = fmaf(q * z, u, u);          // atan(u)

    if (red)      a += PIO4_F;
    if (ay > ax)  a = PIO2_F - a;
    if (x < 0.0f) a = PI_F - a;
    return (y < 0.0f) ? (TWO_PI_F - a) : a;
}

__global__ __launch_bounds__(256, 4) void social_circle_kernel(
    const float* __restrict__ trajs,      // [B, 8, 2]
    const float* __restrict__ nei_trajs,  // [B, 128, 8, 2]
    float* __restrict__ out_sc,           // [B, 8, 3]
    float* __restrict__ out_dir)          // [B, 128]
{
    const int warp = threadIdx.x >> 5;     // 8 warps = 8 rows per CTA
    const int lane = threadIdx.x & 31;
    const int b = blockIdx.x * 8 + warp;

    // obs vector (uniform per warp -> broadcast loads)
    const float* tb = trajs + (size_t)b * 16;
    const float ox7 = tb[14], oy7 = tb[15];
    const float ovx = ox7 - tb[0];
    const float ovy = oy7 - tb[1];
    const float obs_len = approx_len(ovx * ovx + ovy * ovy);

    const float4* base = (const float4*)(nei_trajs + (size_t)b * NNEI * 16);
    float* dirout = out_dir + (size_t)b * NNEI;

    // lane -> (owned partition p = lane>>2, quarter r = lane&3)
    const int p = lane >> 2;
    const int r = lane & 3;
    float s = 0.0f, dd = 0.0f, dir_s = 0.0f, cnt = 0.0f;

    // double-buffered group loads: group g covers neighbors g*32 .. g*32+31,
    // lane l loads neighbor g*32+l (4 float4, warp spans 2KB contiguous)
    float4 A0, A1, A2, A3, B0, B1, B2, B3;
    {
        const int i0 = lane << 2;                  // group 0
        A0 = base[i0]; A1 = base[i0 + 1]; A2 = base[i0 + 2]; A3 = base[i0 + 3];
        const int i1 = (32 + lane) << 2;           // group 1
        B0 = base[i1]; B1 = base[i1 + 1]; B2 = base[i1 + 2]; B3 = base[i1 + 3];
    }

    #pragma unroll
    for (int g = 0; g < 4; g++) {
        const float4 v0 = (g & 1) ? B0 : A0;
        const float4 v1 = (g & 1) ? B1 : A1;
        const float4 v2 = (g & 1) ? B2 : A2;
        const float4 v3 = (g & 1) ? B3 : A3;

        // prefetch group g+2 into the buffer just consumed
        if (g < 2) {
            const int in = (((g + 2) << 5) + lane) << 2;
            if ((g & 1) == 0) {
                A0 = base[in]; A1 = base[in + 1]; A2 = base[in + 2]; A3 = base[in + 3];
            } else {
                B0 = base[in]; B1 = base[in + 1]; B2 = base[in + 2]; B3 = base[in + 3];
            }
        }

        const float ssum = (v0.x + v0.y + v0.z + v0.w)
                         + (v1.x + v1.y + v1.z + v1.w)
                         + (v2.x + v2.y + v2.z + v2.w)
                         + (v3.x + v3.y + v3.z + v3.w);
        const bool valid = (ssum != 0.0f);

        const float nvx = v3.z - v0.x;
        const float nvy = v3.w - v0.y;
        const float nei_len = approx_len(nvx * nvx + nvy * nvy);
        const float f_speed = __fdividef(nei_len + MU_F, obs_len + MU_F);

        const float px = v3.z - ox7;
        const float py = v3.w - oy7;
        const float f_dist = approx_len(px * px + py * py);

        const float d = atan2_2pi(py, px);

        dirout[(g << 5) + lane] = d;   // coalesced 128B store per group

        // bucket key: exact IEEE division (boundary-sensitive); invalid or
        // idx==PARTS -> -1 (never matches any ballot)
        const int idx = (int)(d / (TWO_PI_F / PARTS));
        const int key = (valid && idx < PARTS) ? idx : -1;

        // membership mask of owned partition p over this group's 32 neighbors
        unsigned m = 0;
        #pragma unroll
        for (int pi = 0; pi < PARTS; pi++) {
            const unsigned bm = __ballot_sync(0xffffffffu, key == pi);
            if (p == pi) m = bm;
        }
        cnt += (float)__popc(m);   // FULL warp count (identical on all 4
                                   // lanes of this partition group) — must
                                   // NOT go through the width-4 tree below.

        // quarter-split gather: lane r scans bits [8r, 8r+8); values via shfl.
        unsigned mq = (m >> (r << 3)) & 0xffu;
        while (__any_sync(0xffffffffu, mq != 0u)) {
            const int j = mq ? ((r << 3) + __ffs(mq) - 1) : 0;
            const float a0 = __shfl_sync(0xffffffffu, f_speed, j);
            const float a1 = __shfl_sync(0xffffffffu, f_dist,  j);
            const float a2 = __shfl_sync(0xffffffffu, d,       j);
            if (mq != 0u) {
                s     += a0;
                dd    += a1;
                dir_s += a2;
                mq &= mq - 1u;
            }
        }
    }

    // combine the 4 quarters (aligned groups of 4 lanes) — sums only; cnt is
    // already the full partition count on every lane of the group.
    #pragma unroll
    for (int off = 2; off > 0; off >>= 1) {
        s     += __shfl_down_sync(0xffffffffu, s,     off, 4);
        dd    += __shfl_down_sync(0xffffffffu, dd,    off, 4);
        dir_s += __shfl_down_sync(0xffffffffu, dir_s, off, 4);
    }

    const float inv = __fdividef(1.0f, cnt + CEPS_F);
    s     *= inv;
    dd    *= inv;
    dir_s *= inv;

    // redistribute so lanes 0..23 emit one coalesced 96B store
    const int p2  = (lane * 11) >> 5;     // lane/3 for lane<32
    const int f   = lane - p2 * 3;
    const int src = p2 << 2;              // leader lane of partition p2
    const float a0 = __shfl_sync(0xffffffffu, s,     src);
    const float a1 = __shfl_sync(0xffffffffu, dd,    src);
    const float a2 = __shfl_sync(0xffffffffu, dir_s, src);
    const float outv = (f == 0) ? a0 : ((f == 1) ? a1 : a2);
    if (lane < PARTS * 3) {
        out_sc[(size_t)b * (PARTS * 3) + lane] = outv;
    }
}

extern "C" void kernel_launch(void* const* d_in, const int* in_sizes, int n_in,
                              void* d_out, int out_size) {
    const float* trajs     = (const float*)d_in[0];
    const float* nei_trajs = (const float*)d_in[1];
    float* out = (float*)d_out;

    const int B = in_sizes[0] / 16;   // trajs is [B, 8, 2]

    float* out_sc  = out;                          // [B, 8, 3]
    float* out_dir = out + (size_t)B * PARTS * 3;  // [B, 128]

    social_circle_kernel<<<B / 8, 256>>>(trajs, nei_trajs, out_sc, out_dir);
}